// round 17
// baseline (speedup 1.0000x reference)
#include <cuda_runtime.h>
#include <math.h>

// Shapes fixed by the problem: B=4, C=256, H=W=64, N=4096, Ci=128
#define B_    4
#define C_    256
#define N_    4096
#define CI_   128
#define GRID_ 512              // blocks; 2 tiles each; all resident (4/SM*148=592)
#define TPB_  256
#define TJ_   16               // pixels per tile

// Scratch (allocation-free rule: __device__ globals; zero-initialized once)
__device__ float g_xbar[B_ * C_];            // per-(b,c) SUM accumulator (RED);
                                             // producers consume then reset to 0
__device__ float g_w[B_ * C_];
__device__ float g_s[B_];
__device__ unsigned long long g_arrive;      // monotone across graph replays
__device__ unsigned long long g_wdone;       // monotone across graph replays

__global__ __launch_bounds__(TPB_, 4) void k_all(
    const float* __restrict__ x,
    const float* __restrict__ theta_w, const float* __restrict__ theta_b,
    const float* __restrict__ phi_w,  const float* __restrict__ phi_b,
    float* __restrict__ out)
{
    const int tid  = threadIdx.x;
    const int lane = tid & 31, warp = tid >> 5;
    const int jloc = tid & 15;               // pixel within tile
    const int csub = tid >> 4;               // 0..15 (16 channels each)

    // SMEM: x cached with +1 pad (17) so csub-halves of a warp hit disjoint banks
    __shared__ float xs[2][C_][17];          // 34816 B
    __shared__ float sums_s[C_];
    __shared__ float ws[C_];
    __shared__ float xb_s[C_];
    __shared__ float tb_s[CI_];
    __shared__ float part[16][TJ_];
    __shared__ float conf_s[TJ_];
    __shared__ float sb_s;
    __shared__ unsigned long long k_rep;

    // Full-coverage L2 prefetch of weights (theta_w: blocks 0-3, phi_w: 4-7;
    // each matrix = 128KB = 4 blocks x 256 thr x 128B lines).
    if (blockIdx.x < 8) {
        const char* base = (blockIdx.x < 4) ? (const char*)theta_w
                                            : (const char*)phi_w;
        const char* p = base + ((size_t)((blockIdx.x & 3) * TPB_ + tid)) * 128;
        asm volatile("prefetch.global.L2 [%0];" :: "l"(p));
    }

    // ---- Phase A: read x once into SMEM; RED per-tile channel sums ----
    #pragma unroll
    for (int s = 0; s < 2; ++s) {
        const int tile = blockIdx.x + s * GRID_;      // 0..1023
        const int b = tile >> 8;
        const int t = tile & 255;
        const int j = t * TJ_ + jloc;
        const float* xp = x + ((size_t)(b * C_ + csub * 16)) * N_ + j;

        float v[16];
        #pragma unroll
        for (int i = 0; i < 16; ++i) v[i] = __ldg(xp + (size_t)i * N_);
        #pragma unroll
        for (int i = 0; i < 16; ++i) xs[s][csub * 16 + i][jloc] = v[i];
        #pragma unroll
        for (int i = 0; i < 16; ++i) {
            float u = v[i];                           // reduce over 16 jloc lanes
            u += __shfl_xor_sync(0xffffffffu, u, 1);
            u += __shfl_xor_sync(0xffffffffu, u, 2);
            u += __shfl_xor_sync(0xffffffffu, u, 4);
            u += __shfl_xor_sync(0xffffffffu, u, 8);
            if ((lane & 15) == 0) sums_s[csub * 16 + i] = u;
        }
        __syncthreads();
        atomicAdd(&g_xbar[b * C_ + tid], sums_s[tid]);   // RED, no return
        __syncthreads();                                  // sums_s reuse guard
    }

    // ---- Arrival (release): ticket defines this replay's index k ----
    __threadfence();
    if (tid == 0) {
        unsigned long long a1 = atomicAdd(&g_arrive, 1ULL) + 1ULL;
        k_rep = (a1 + (unsigned long long)(GRID_ - 1)) / (unsigned long long)GRID_;
    }
    __syncthreads();
    const unsigned long long krep = k_rep;

    // ---- Producers: blocks 0..3 -> w[bp,:], s[bp] ----
    if (blockIdx.x < B_) {
        const int bp = blockIdx.x;
        if (tid == 0) {
            volatile unsigned long long* ap = &g_arrive;
            long guard = 0;
            while (*ap < krep * (unsigned long long)GRID_ && guard < (1L << 26)) {
                __nanosleep(32); ++guard;
            }
        }
        __syncthreads();
        __threadfence();                               // acquire
        xb_s[tid] = g_xbar[bp * C_ + tid] * (1.0f / N_);
        g_xbar[bp * C_ + tid] = 0.0f;                  // reset for next replay
        __syncthreads();

        for (int i = 0; i < CI_ / 8; ++i) {
            const int kk = warp * (CI_ / 8) + i;
            const float* tw = theta_w + (size_t)kk * C_;
            float a = 0.f;
            #pragma unroll
            for (int c = lane; c < C_; c += 32) a += __ldg(tw + c) * xb_s[c];
            #pragma unroll
            for (int o = 16; o; o >>= 1) a += __shfl_xor_sync(0xffffffffu, a, o);
            if (lane == 0) tb_s[kk] = a + __ldg(theta_b + kk);
        }
        __syncthreads();
        float wacc = 0.f;
        #pragma unroll 8
        for (int kk = 0; kk < CI_; ++kk)
            wacc += tb_s[kk] * __ldg(phi_w + (size_t)kk * C_ + tid);
        g_w[bp * C_ + tid] = wacc;
        if (warp == 0) {
            float a = 0.f;
            #pragma unroll
            for (int kk = lane; kk < CI_; kk += 32) a += tb_s[kk] * __ldg(phi_b + kk);
            #pragma unroll
            for (int o = 16; o; o >>= 1) a += __shfl_xor_sync(0xffffffffu, a, o);
            if (lane == 0) g_s[bp] = a;
        }
        __threadfence();                               // publish g_w/g_s
        __syncthreads();
        if (tid == 0) atomicAdd(&g_wdone, 1ULL);       // RED
    }

    // ---- All blocks: wait until all 4 producers of THIS replay are done ----
    if (tid == 0) {
        volatile unsigned long long* wp = &g_wdone;
        long guard = 0;
        while (*wp < krep * (unsigned long long)B_ && guard < (1L << 26)) {
            __nanosleep(32); ++guard;
        }
    }
    __syncthreads();

    // ---- Phase C: dot / sigmoid / scale, x from SMEM; write out ----
    #pragma unroll
    for (int s = 0; s < 2; ++s) {
        const int tile = blockIdx.x + s * GRID_;
        const int b = tile >> 8;
        const int t = tile & 255;
        const int j = t * TJ_ + jloc;

        ws[tid] = __ldcg(&g_w[b * C_ + tid]);
        if (tid == 0) sb_s = __ldcg(&g_s[b]);
        __syncthreads();

        float acc = 0.f;
        #pragma unroll
        for (int i = 0; i < 16; ++i)
            acc += ws[csub * 16 + i] * xs[s][csub * 16 + i][jloc];
        part[csub][jloc] = acc;
        __syncthreads();

        if (tid < TJ_) {
            float m = 0.f;
            #pragma unroll
            for (int k2 = 0; k2 < 16; ++k2) m += part[k2][tid];
            m = (m + sb_s) * (1.0f / N_);
            conf_s[tid] = 1.0f / (1.0f + expf(-m));
        }
        __syncthreads();

        const float cf = conf_s[jloc];
        float* op = out + ((size_t)(b * C_ + csub * 16)) * N_ + j;
        #pragma unroll
        for (int i = 0; i < 16; ++i)
            op[(size_t)i * N_] = cf * xs[s][csub * 16 + i][jloc];
        __syncthreads();                               // ws/conf reuse guard
    }
}

// ---------------------------------------------------------------------------
extern "C" void kernel_launch(void* const* d_in, const int* in_sizes, int n_in,
                              void* d_out, int out_size) {
    const float* x       = (const float*)d_in[0];
    const float* theta_w = (const float*)d_in[1];
    const float* theta_b = (const float*)d_in[2];
    const float* phi_w   = (const float*)d_in[3];
    const float* phi_b   = (const float*)d_in[4];
    float* out = (float*)d_out;

    k_all<<<GRID_, TPB_>>>(x, theta_w, theta_b, phi_w, phi_b, out);
}